// round 16
// baseline (speedup 1.0000x reference)
#include <cuda_runtime.h>
#include <math.h>

#define H 512
#define B 256
#define T 512
#define DIN 64
#define NCTA 128
#define NTHR 256
#define HB (H * B)

// ---------------- persistent device state (allocation-free) ----------------
__device__ float g_xT[(size_t)T * DIN * B];          // x transposed: [t][d][b] (32 MB)
__device__ float g_h1seqT[(size_t)T * H * B];        // layer-0 output: [t][j][b] (256 MB)
__device__ float g_hT0[2][HB];                       // layer-0 hidden, [j][b], double-buffered
__device__ float g_hT1[2][HB];                       // layer-1 hidden
__device__ float g_cT0[HB];                          // cells, [j][b]
__device__ float g_cT1[HB];
__device__ unsigned g_bar_cnt;
__device__ volatile unsigned g_bar_phase;

// ---------------- helpers ----------------
#define FMAX2(d, a, b) asm("fma.rn.f32x2 %0, %1, %2, %0;" : "+l"(d) : "l"(a), "l"(b))

__device__ __forceinline__ unsigned long long splat2(float v) {
    unsigned long long r;
    unsigned u = __float_as_uint(v);
    asm("mov.b64 %0, {%1, %1};" : "=l"(r) : "r"(u));
    return r;
}

__device__ __forceinline__ float2 unpack2(unsigned long long v) {
    float2 r;
    r.x = __uint_as_float((unsigned)v);
    r.y = __uint_as_float((unsigned)(v >> 32));
    return r;
}

__device__ __forceinline__ void grid_barrier(unsigned target) {
    __threadfence();
    __syncthreads();
    if (threadIdx.x == 0) {
        unsigned a = atomicAdd(&g_bar_cnt, 1);
        if (a == gridDim.x - 1) {
            g_bar_cnt = 0;
            __threadfence();
            g_bar_phase = target;           // release
        } else {
            while (g_bar_phase < target) {} // spin
        }
        __threadfence();
    }
    __syncthreads();
}

// acc[unit][(i,f)/(g,o)][batch] as f32x2 over gate pairs.
// One k step: A = 2 batches (splat), W = 16 floats [u][i,f,g,o] (4 uniform LDS.128).
__device__ __forceinline__ void fma16(
    unsigned long long (&acc)[4][2][2], float2 av, const float* __restrict__ Wk)
{
    longlong2 w0 = *(const longlong2*)(Wk);
    longlong2 w1 = *(const longlong2*)(Wk + 4);
    longlong2 w2 = *(const longlong2*)(Wk + 8);
    longlong2 w3 = *(const longlong2*)(Wk + 12);
    unsigned long long a0 = splat2(av.x);
    unsigned long long a1 = splat2(av.y);
    FMAX2(acc[0][0][0], a0, (unsigned long long)w0.x);
    FMAX2(acc[0][0][1], a1, (unsigned long long)w0.x);
    FMAX2(acc[0][1][0], a0, (unsigned long long)w0.y);
    FMAX2(acc[0][1][1], a1, (unsigned long long)w0.y);
    FMAX2(acc[1][0][0], a0, (unsigned long long)w1.x);
    FMAX2(acc[1][0][1], a1, (unsigned long long)w1.x);
    FMAX2(acc[1][1][0], a0, (unsigned long long)w1.y);
    FMAX2(acc[1][1][1], a1, (unsigned long long)w1.y);
    FMAX2(acc[2][0][0], a0, (unsigned long long)w2.x);
    FMAX2(acc[2][0][1], a1, (unsigned long long)w2.x);
    FMAX2(acc[2][1][0], a0, (unsigned long long)w2.y);
    FMAX2(acc[2][1][1], a1, (unsigned long long)w2.y);
    FMAX2(acc[3][0][0], a0, (unsigned long long)w3.x);
    FMAX2(acc[3][0][1], a1, (unsigned long long)w3.x);
    FMAX2(acc[3][1][0], a0, (unsigned long long)w3.y);
    FMAX2(acc[3][1][1], a1, (unsigned long long)w3.y);
}

// Accumulate nk rows of segment: A rows [k][B] from global (L2), W rows from SMEM.
__device__ __forceinline__ void seg_accum(
    unsigned long long (&acc)[4][2][2],
    const float* __restrict__ Aseg, const float* __restrict__ Wseg,
    int nk, int tl)
{
    const float* ap = Aseg + 2 * tl;
    #pragma unroll 8
    for (int k = 0; k < nk; k++) {
        float2 av = *(const float2*)(ap + (size_t)k * B);
        fma16(acc, av, Wseg + k * 16);
    }
}

__device__ __forceinline__ void acc_zero(unsigned long long (&acc)[4][2][2]) {
    #pragma unroll
    for (int u = 0; u < 4; u++)
        #pragma unroll
        for (int p = 0; p < 2; p++)
            #pragma unroll
            for (int b = 0; b < 2; b++) acc[u][p][b] = 0ull;
}

__device__ __forceinline__ void red_store(
    unsigned long long* __restrict__ red,
    const unsigned long long (&acc)[4][2][2], int tl)
{
    #pragma unroll
    for (int u = 0; u < 4; u++)
        #pragma unroll
        for (int p = 0; p < 2; p++)
            #pragma unroll
            for (int b = 0; b < 2; b++)
                red[(((u * 2 + p) * 2 + b) * 128) + tl] = acc[u][p][b];
}

// reduce partner's half + fused cell update (gate order i,f,g,o)
__device__ __forceinline__ void reduce_update(
    unsigned long long (&acc)[4][2][2],
    const unsigned long long* __restrict__ red,
    const float* __restrict__ bsh,          // [u*4+g] bias sums for this CTA
    float* __restrict__ cbuf, float* __restrict__ hout, float* __restrict__ seq,
    int jblk, int tl)
{
    #pragma unroll
    for (int u = 0; u < 4; u++) {
        #pragma unroll
        for (int p = 0; p < 2; p++)
            #pragma unroll
            for (int b = 0; b < 2; b++) {
                float2 s = unpack2(red[(((u * 2 + p) * 2 + b) * 128) + tl]);
                float2 m = unpack2(acc[u][p][b]);
                acc[u][p][b] = ((unsigned long long)__float_as_uint(m.y + s.y) << 32)
                             | __float_as_uint(m.x + s.x);
            }
        int j = jblk + u;
        float* cp_ = cbuf + (size_t)j * B + 2 * tl;
        float2 cv = *(const float2*)cp_;
        float cold[2] = {cv.x, cv.y};
        float cn2[2], hn2[2];
        #pragma unroll
        for (int b = 0; b < 2; b++) {
            float2 pif = unpack2(acc[u][0][b]);
            float2 pgo = unpack2(acc[u][1][b]);
            float gi = pif.x + bsh[u * 4 + 0];
            float gf = pif.y + bsh[u * 4 + 1];
            float gg = pgo.x + bsh[u * 4 + 2];
            float go = pgo.y + bsh[u * 4 + 3];
            float si = 1.f / (1.f + expf(-gi));
            float sf = 1.f / (1.f + expf(-gf));
            float so = 1.f / (1.f + expf(-go));
            float cn = sf * cold[b] + si * tanhf(gg);
            cn2[b] = cn;
            hn2[b] = so * tanhf(cn);
        }
        *(float2*)cp_ = make_float2(cn2[0], cn2[1]);
        float2 hv = make_float2(hn2[0], hn2[1]);
        *(float2*)(hout + (size_t)j * B + 2 * tl) = hv;
        if (seq)
            *(float2*)(seq + (size_t)j * B + 2 * tl) = hv;
    }
}

// ---------------- single persistent kernel ----------------
// 128 CTAs x 256 threads (8 warps, 2/SMSP). CTA bx owns hidden units [4bx,4bx+4),
// all 256 batch, all 4 gates. Warp-group g = tid>>7 handles half the k-range
// (k-split); thread tile = 2 batches x 4 units x 4 gates = 16 f32x2 per k.
// A is loaded DIRECTLY from global (L2-resident) -- no SMEM staging, no cp.async,
// no per-chunk syncs. SMEM holds only W (both layers) + 16KB reduction buffer.
__global__ __launch_bounds__(NTHR, 1) void lstm_persist(
    const float* __restrict__ x,
    const float* __restrict__ W_ih0, const float* __restrict__ W_hh0,
    const float* __restrict__ b_ih0, const float* __restrict__ b_hh0,
    const float* __restrict__ W_ih1, const float* __restrict__ W_hh1,
    const float* __restrict__ b_ih1, const float* __restrict__ b_hh1,
    const float* __restrict__ fcW,  const float* __restrict__ fcb,
    float* __restrict__ out)
{
    extern __shared__ char smem[];
    float* Wsh0 = (float*)smem;                            // 576*16*4  = 36864
    float* Wsh1 = (float*)(smem + 36864);                  // 1024*16*4 = 65536
    unsigned long long* red = (unsigned long long*)(smem + 36864 + 65536); // 16KB
    float* bsh = (float*)(smem + 36864 + 65536 + 16384);   // 2*16 floats

    const int tid  = threadIdx.x;
    const int grp  = tid >> 7;        // k-split group (warps 0-3 vs 4-7)
    const int tl   = tid & 127;       // batches 2*tl, 2*tl+1
    const int jblk = blockIdx.x * 4;  // CTA's first hidden unit

    const unsigned base = g_bar_phase;
    unsigned phase = 0;

    // ---- init hidden/cell state ----
    for (int i = blockIdx.x * NTHR + tid; i < HB; i += NCTA * NTHR) {
        g_hT0[0][i] = 0.f; g_cT0[i] = 0.f;
        g_hT1[0][i] = 0.f; g_cT1[i] = 0.f;
    }

    // ---- transpose x: [b][t][d] -> xT[t][d][b] (tile in red region) ----
    {
        float* tile = (float*)red;   // 32*65 floats = 8320 B
        for (int ti = blockIdx.x; ti < T * (B / 32); ti += NCTA) {
            int t = ti >> 3;
            int bblk = (ti & 7) * 32;
            for (int i = tid; i < 32 * 64; i += NTHR) {
                int b = i >> 6, d = i & 63;
                tile[b * 65 + d] = x[((size_t)(bblk + b) * T + t) * DIN + d];
            }
            __syncthreads();
            for (int i = tid; i < 32 * 64; i += NTHR) {
                int d = i >> 5, b = i & 31;
                g_xT[((size_t)t * DIN + d) * B + bblk + b] = tile[b * 65 + d];
            }
            __syncthreads();
        }
    }

    // ---- W slices into SMEM: Wsh[k][unit(4)][gate(4)] ----
    for (int idx = tid; idx < (DIN + H) * 16; idx += NTHR) {
        int k = idx >> 4, u = (idx >> 2) & 3, g = idx & 3;
        int row = g * H + jblk + u;
        Wsh0[idx] = (k < DIN) ? W_ih0[(size_t)row * DIN + k]
                              : W_hh0[(size_t)row * H + (k - DIN)];
    }
    for (int idx = tid; idx < (H + H) * 16; idx += NTHR) {
        int k = idx >> 4, u = (idx >> 2) & 3, g = idx & 3;
        int row = g * H + jblk + u;
        Wsh1[idx] = (k < H) ? W_ih1[(size_t)row * H + k]
                            : W_hh1[(size_t)row * H + (k - H)];
    }
    if (tid < 32) {
        int u = (tid >> 2) & 3, g = tid & 3, l = tid >> 4;
        int row = g * H + jblk + u;
        bsh[tid] = l ? (b_ih1[row] + b_hh1[row]) : (b_ih0[row] + b_hh0[row]);
    }

    grid_barrier(base + ++phase);

    // ---- epoch loop: e in [0,T]; layer0@t=e (e<T), layer1@t=e-1 (e>0) ----
    unsigned long long acc[4][2][2];
    for (int e = 0; e <= T; e++) {
        const bool L0a = (e < T), L1a = (e > 0);
        const int t0 = e, t1 = e - 1;

        if (L0a) {
            const float* h0in = g_hT0[t0 & 1];
            acc_zero(acc);
            // x segment: 64 rows, half each; h segment: 512 rows, half each
            seg_accum(acc, g_xT + (size_t)t0 * DIN * B + (size_t)grp * 32 * B,
                      Wsh0 + (size_t)grp * 32 * 16, 32, tl);
            seg_accum(acc, h0in + (size_t)grp * 256 * B,
                      Wsh0 + (size_t)(64 + grp * 256) * 16, 256, tl);
            if (grp == 1) red_store(red, acc, tl);
        }
        __syncthreads();
        if (L0a && grp == 0) {
            reduce_update(acc, red, bsh, g_cT0, g_hT0[(t0 + 1) & 1],
                          g_h1seqT + (size_t)t0 * H * B, jblk, tl);
        }
        if (L1a) {
            const float* h2in = g_hT1[t1 & 1];
            acc_zero(acc);
            seg_accum(acc, g_h1seqT + (size_t)t1 * H * B + (size_t)grp * 256 * B,
                      Wsh1 + (size_t)grp * 256 * 16, 256, tl);
            seg_accum(acc, h2in + (size_t)grp * 256 * B,
                      Wsh1 + (size_t)(512 + grp * 256) * 16, 256, tl);
            if (grp == 0) red_store(red, acc, tl);
        }
        __syncthreads();
        if (L1a && grp == 1) {
            reduce_update(acc, red, bsh + 16, g_cT1, g_hT1[(t1 + 1) & 1],
                          nullptr, jblk, tl);
        }

        grid_barrier(base + ++phase);
    }

    // ---------------- FC epilogue: out[b] = h2_last . fcW + fcb ----------------
    const float* hfin = g_hT1[0];   // last layer-1 write (t1=511) -> buffer 0
    int b0 = blockIdx.x * 2;
    float s0 = 0.f, s1 = 0.f;
    for (int j = tid; j < H; j += NTHR) {
        float w = fcW[j];
        s0 += w * hfin[(size_t)j * B + b0];
        s1 += w * hfin[(size_t)j * B + b0 + 1];
    }
    float* rf = (float*)red;
    rf[tid] = s0; rf[NTHR + tid] = s1;
    __syncthreads();
    for (int off = NTHR / 2; off > 0; off >>= 1) {
        if (tid < off) {
            rf[tid] += rf[tid + off];
            rf[NTHR + tid] += rf[NTHR + tid + off];
        }
        __syncthreads();
    }
    if (tid == 0) {
        out[b0]     = rf[0]    + fcb[0];
        out[b0 + 1] = rf[NTHR] + fcb[0];
    }
}

// ---------------- launch ----------------
extern "C" void kernel_launch(void* const* d_in, const int* in_sizes, int n_in,
                              void* d_out, int out_size)
{
    const float* x     = (const float*)d_in[0];
    const float* W_ih0 = (const float*)d_in[1];
    const float* W_hh0 = (const float*)d_in[2];
    const float* b_ih0 = (const float*)d_in[3];
    const float* b_hh0 = (const float*)d_in[4];
    const float* W_ih1 = (const float*)d_in[5];
    const float* W_hh1 = (const float*)d_in[6];
    const float* b_ih1 = (const float*)d_in[7];
    const float* b_hh1 = (const float*)d_in[8];
    const float* fc_W  = (const float*)d_in[9];
    const float* fc_b  = (const float*)d_in[10];
    float* out = (float*)d_out;

    const int smem_bytes = 36864 + 65536 + 16384 + 256;   // 119040
    cudaFuncSetAttribute(lstm_persist,
                         cudaFuncAttributeMaxDynamicSharedMemorySize, smem_bytes);

    lstm_persist<<<NCTA, NTHR, smem_bytes>>>(x,
                                             W_ih0, W_hh0, b_ih0, b_hh0,
                                             W_ih1, W_hh1, b_ih1, b_hh1,
                                             fc_W, fc_b, out);
}